// round 2
// baseline (speedup 1.0000x reference)
#include <cuda_runtime.h>
#include <math.h>

#define NPTS 512
#define DCLS 9
#define LLAT 32
#define ENTRY_FLOATS 20   // 4 points * (x,y,z,w,c) SoA within entry
#define NENT 128          // 512 / 4
#define CHUNK_ENT 8       // 8 entries = 32 points per chunk
#define NCHUNK 16

typedef unsigned long long u64;

__device__ __forceinline__ u64 ffma2(u64 a, u64 b, u64 c) {
    u64 d;
    asm("fma.rn.f32x2 %0, %1, %2, %3;" : "=l"(d) : "l"(a), "l"(b), "l"(c));
    return d;
}
__device__ __forceinline__ u64 pack2(float lo, float hi) {
    u64 r;
    asm("mov.b64 %0, {%1, %2};" : "=l"(r) : "f"(lo), "f"(hi));
    return r;
}
__device__ __forceinline__ float2 unpack2(u64 v) {
    float2 r;
    asm("mov.b64 {%0, %1}, %2;" : "=f"(r.x), "=f"(r.y) : "l"(v));
    return r;
}

__device__ __forceinline__ float warpReduceSum(float v) {
    #pragma unroll
    for (int o = 16; o > 0; o >>= 1)
        v += __shfl_down_sync(0xFFFFFFFFu, v, o);
    return v;
}

// Find argmax_m of score(m) = q . p_m - 0.5*|p_m|^2 over 512 points stored in sarr.
// Chunked: track per-chunk max with bare FMNMX, then rescan the winning chunk
// with bitwise-identical arithmetic to recover the first-occurrence index.
__device__ __forceinline__ void nn_search(const float* __restrict__ sarr,
                                          u64 qx, u64 qy, u64 qz, u64 qw,
                                          float& outScore, int& outIdx)
{
    float bd = -3.402823466e38f;
    int bc = 0;
    #pragma unroll 1
    for (int c = 0; c < NCHUNK; c++) {
        const float* cb = sarr + c * (CHUNK_ENT * ENTRY_FLOATS);
        float cbd = -3.402823466e38f;
        #pragma unroll
        for (int e = 0; e < CHUNK_ENT; e++) {
            const ulonglong2* p = reinterpret_cast<const ulonglong2*>(cb + e * ENTRY_FLOATS);
            ulonglong2 vx = p[0], vy = p[1], vz = p[2], vw = p[3], vc = p[4];
            u64 s01 = ffma2(qx, vx.x, ffma2(qy, vy.x, ffma2(qz, vz.x, ffma2(qw, vw.x, vc.x))));
            u64 s23 = ffma2(qx, vx.y, ffma2(qy, vy.y, ffma2(qz, vz.y, ffma2(qw, vw.y, vc.y))));
            float2 a = unpack2(s01);
            float2 b = unpack2(s23);
            cbd = fmaxf(cbd, a.x);
            cbd = fmaxf(cbd, a.y);
            cbd = fmaxf(cbd, b.x);
            cbd = fmaxf(cbd, b.y);
        }
        if (cbd > bd) { bd = cbd; bc = c; }
    }

    // rescan winning chunk for first index achieving bd (bitwise identical recompute)
    int idx = -1;
    const float* cb = sarr + bc * (CHUNK_ENT * ENTRY_FLOATS);
    #pragma unroll
    for (int e = 0; e < CHUNK_ENT; e++) {
        const ulonglong2* p = reinterpret_cast<const ulonglong2*>(cb + e * ENTRY_FLOATS);
        ulonglong2 vx = p[0], vy = p[1], vz = p[2], vw = p[3], vc = p[4];
        u64 s01 = ffma2(qx, vx.x, ffma2(qy, vy.x, ffma2(qz, vz.x, ffma2(qw, vw.x, vc.x))));
        u64 s23 = ffma2(qx, vx.y, ffma2(qy, vy.y, ffma2(qz, vz.y, ffma2(qw, vw.y, vc.y))));
        float2 a = unpack2(s01);
        float2 b = unpack2(s23);
        int base = bc * 32 + e * 4;
        if (idx < 0 && a.x == bd) idx = base + 0;
        if (idx < 0 && a.y == bd) idx = base + 1;
        if (idx < 0 && b.x == bd) idx = base + 2;
        if (idx < 0 && b.y == bd) idx = base + 3;
    }
    outScore = bd;
    outIdx = (idx < 0) ? 0 : idx;
}

__global__ __launch_bounds__(NPTS, 2) void loss_kernel(
    const float* __restrict__ kine_input,   // [B, N, 4]
    const float* __restrict__ class_input,  // [B, N, 9]
    const float* __restrict__ kine_pred,    // [B, N, 4]
    const float* __restrict__ class_pred,   // [B, N, 9]
    const float* __restrict__ mu,           // [B, 32]
    const float* __restrict__ log_var,      // [B, 32]
    float* __restrict__ out)                // [B]
{
    const int b = blockIdx.x;
    const int t = threadIdx.x;

    __shared__ __align__(16) float sA[NENT * ENTRY_FLOATS];  // input points
    __shared__ __align__(16) float sB[NENT * ENTRY_FLOATS];  // pred points
    __shared__ int   hin[DCLS];
    __shared__ int   hpred[DCLS];
    __shared__ float red[16];

    if (t < DCLS) { hin[t] = 0; hpred[t] = 0; }

    // ---- load my two points, stage SoA-packed entries into smem ----
    const float4 x = reinterpret_cast<const float4*>(kine_input)[b * NPTS + t];
    const float myx2 = x.x * x.x + x.y * x.y + x.z * x.z + x.w * x.w;
    const float4 y = reinterpret_cast<const float4*>(kine_pred)[b * NPTS + t];
    const float myy2 = y.x * y.x + y.y * y.y + y.z * y.z + y.w * y.w;

    {
        const int e = t >> 2, l = t & 3;
        float* ba = sA + e * ENTRY_FLOATS;
        ba[l] = x.x; ba[4 + l] = x.y; ba[8 + l] = x.z; ba[12 + l] = x.w;
        ba[16 + l] = -0.5f * myx2;
        float* bb = sB + e * ENTRY_FLOATS;
        bb[l] = y.x; bb[4 + l] = y.y; bb[8 + l] = y.z; bb[12 + l] = y.w;
        bb[16 + l] = -0.5f * myy2;
    }

    // ---- class rows into registers; labels (first-max index) ----
    float ci[DCLS], cp[DCLS];
    {
        const float* cip = class_input + ((size_t)b * NPTS + t) * DCLS;
        const float* cpp = class_pred  + ((size_t)b * NPTS + t) * DCLS;
        #pragma unroll
        for (int d = 0; d < DCLS; d++) { ci[d] = cip[d]; cp[d] = cpp[d]; }
    }
    int li = 0, lp = 0;
    {
        float mi = ci[0], mp = cp[0];
        #pragma unroll
        for (int d = 1; d < DCLS; d++) {
            if (ci[d] > mi) { mi = ci[d]; li = d; }
            if (cp[d] > mp) { mp = cp[d]; lp = d; }
        }
    }

    __syncthreads();

    atomicAdd(&hin[li], 1);
    atomicAdd(&hpred[lp], 1);

    // ---- pass 1: my input point vs all pred points (search sB) ----
    float s1score; int bi1;
    {
        const u64 qx = pack2(x.x, x.x), qy = pack2(x.y, x.y);
        const u64 qz = pack2(x.z, x.z), qw = pack2(x.w, x.w);
        nn_search(sB, qx, qy, qz, qw, s1score, bi1);
    }
    const float dist1 = fmaxf(fmaf(-2.0f, s1score, myx2), 0.0f);

    // ---- pass 2: my pred point vs all input points (search sA) ----
    float s2score; int bi2;
    {
        const u64 qx = pack2(y.x, y.x), qy = pack2(y.y, y.y);
        const u64 qz = pack2(y.z, y.z), qw = pack2(y.w, y.w);
        nn_search(sA, qx, qy, qz, qw, s2score, bi2);
    }
    const float dist2 = fmaxf(fmaf(-2.0f, s2score, myy2), 0.0f);

    // ---- classification gathers ----
    float s1 = 0.0f, s2 = 0.0f;
    {
        const float* gcp = class_pred  + ((size_t)b * NPTS + bi1) * DCLS;
        const float* gci = class_input + ((size_t)b * NPTS + bi2) * DCLS;
        #pragma unroll
        for (int d = 0; d < DCLS; d++) {
            s1 = fmaf(gcp[d], ci[d], s1);
            s2 = fmaf(gci[d], cp[d], s2);
        }
    }

    float r = dist1 + dist2 - s1 - s2;

    // ---- block reduction ----
    const int lane = t & 31;
    const int wid  = t >> 5;
    float v = warpReduceSum(r);
    if (lane == 0) red[wid] = v;
    __syncthreads();
    if (wid == 0) {
        v = (lane < 16) ? red[lane] : 0.0f;
        v = warpReduceSum(v);
        if (lane == 0) red[0] = v;
    }
    __syncthreads();

    if (t == 0) {
        float S = red[0];   // chamfer_loss + class_loss

        float cn;
        {
            float d0 = fabsf((float)(hpred[0] - hin[0]));
            float d8 = fabsf((float)(hpred[DCLS - 1] - hin[DCLS - 1]));
            cn = d0 * 2.0f + d8 * 100.0f;
            #pragma unroll
            for (int c = 1; c < DCLS - 1; c++)
                cn += fabsf((float)(hpred[c] - hin[c]));
        }

        float kl = 0.0f;
        const float* mub = mu      + (size_t)b * LLAT;
        const float* lvb = log_var + (size_t)b * LLAT;
        #pragma unroll
        for (int l = 0; l < LLAT; l++) {
            float m  = mub[l];
            float lv = lvb[l];
            kl += 1.0f + lv - m * m - expf(lv);
        }
        kl = -0.5f * kl;

        out[b] = 0.99f * (S + 0.001f * cn) + 0.01f * kl;
    }
}

extern "C" void kernel_launch(void* const* d_in, const int* in_sizes, int n_in,
                              void* d_out, int out_size)
{
    const float* kine_input  = (const float*)d_in[0];
    const float* class_input = (const float*)d_in[1];
    const float* kine_pred   = (const float*)d_in[2];
    const float* class_pred  = (const float*)d_in[3];
    const float* mu          = (const float*)d_in[4];
    const float* log_var     = (const float*)d_in[5];

    const int B = in_sizes[4] / LLAT;   // mu is [B, 32]

    loss_kernel<<<B, NPTS>>>(kine_input, class_input, kine_pred, class_pred,
                             mu, log_var, (float*)d_out);
}

// round 3
// speedup vs baseline: 1.5552x; 1.5552x over previous
#include <cuda_runtime.h>
#include <math.h>

#define NPTS 512
#define DCLS 9
#define LLAT 32
#define THREADS 256
#define HALF 128
#define QPT 4
#define EF 20      // floats per entry (4 points SoA: x0-3,y0-3,z0-3,w0-3,n0-3)
#define NENT 128
#define CE 4       // entries per chunk (16 candidates)
#define NCHUNK 32

typedef unsigned long long u64;

__device__ __forceinline__ u64 ffma2(u64 a, u64 b, u64 c) {
    u64 d; asm("fma.rn.f32x2 %0,%1,%2,%3;" : "=l"(d) : "l"(a), "l"(b), "l"(c)); return d;
}
__device__ __forceinline__ u64 fmul2(u64 a, u64 b) {
    u64 d; asm("mul.rn.f32x2 %0,%1,%2;" : "=l"(d) : "l"(a), "l"(b)); return d;
}
__device__ __forceinline__ u64 fadd2(u64 a, u64 b) {
    u64 d; asm("add.rn.f32x2 %0,%1,%2;" : "=l"(d) : "l"(a), "l"(b)); return d;
}
__device__ __forceinline__ u64 pack2(float lo, float hi) {
    u64 r; asm("mov.b64 %0,{%1,%2};" : "=l"(r) : "f"(lo), "f"(hi)); return r;
}
__device__ __forceinline__ float2 unpack2(u64 v) {
    float2 r; asm("mov.b64 {%0,%1},%2;" : "=f"(r.x), "=f"(r.y) : "l"(v)); return r;
}

__device__ __forceinline__ float warpReduceSum(float v) {
    #pragma unroll
    for (int o = 16; o > 0; o >>= 1)
        v += __shfl_down_sync(0xFFFFFFFFu, v, o);
    return v;
}

__global__ __launch_bounds__(THREADS, 2) void loss_kernel(
    const float* __restrict__ kine_input,   // [B, N, 4]
    const float* __restrict__ class_input,  // [B, N, 9]
    const float* __restrict__ kine_pred,    // [B, N, 4]
    const float* __restrict__ class_pred,   // [B, N, 9]
    const float* __restrict__ mu,           // [B, 32]
    const float* __restrict__ log_var,      // [B, 32]
    float* __restrict__ out)                // [B]
{
    const int b = blockIdx.x;
    const int t = threadIdx.x;

    __shared__ __align__(16) float sA[NENT * EF];  // input points, entry-packed
    __shared__ __align__(16) float sB[NENT * EF];  // pred points, entry-packed
    __shared__ int   hin[DCLS];
    __shared__ int   hpred[DCLS];
    __shared__ float red[8];

    if (t < DCLS) { hin[t] = 0; hpred[t] = 0; }

    // ---- stage points (2 per side per thread) into SoA entries ----
    #pragma unroll
    for (int p = t; p < NPTS; p += THREADS) {
        float4 x = reinterpret_cast<const float4*>(kine_input)[b * NPTS + p];
        float nx = x.x * x.x + x.y * x.y + x.z * x.z + x.w * x.w;
        int e = p >> 2, l = p & 3;
        float* ba = sA + e * EF;
        ba[l] = x.x; ba[4 + l] = x.y; ba[8 + l] = x.z; ba[12 + l] = x.w; ba[16 + l] = nx;

        float4 y = reinterpret_cast<const float4*>(kine_pred)[b * NPTS + p];
        float ny = y.x * y.x + y.y * y.y + y.z * y.z + y.w * y.w;
        float* bb = sB + e * EF;
        bb[l] = y.x; bb[4 + l] = y.y; bb[8 + l] = y.z; bb[12 + l] = y.w; bb[16 + l] = ny;
    }

    // ---- labels for histogram (2 input rows + 2 pred rows per thread) ----
    int lab_i[2], lab_p[2];
    #pragma unroll
    for (int r2 = 0; r2 < 2; r2++) {
        int p = t + r2 * THREADS;
        const float* ci = class_input + ((size_t)b * NPTS + p) * DCLS;
        const float* cp = class_pred  + ((size_t)b * NPTS + p) * DCLS;
        int li = 0, lp = 0;
        float mi = ci[0], mp = cp[0];
        #pragma unroll
        for (int d = 1; d < DCLS; d++) {
            float a = ci[d], q = cp[d];
            if (a > mi) { mi = a; li = d; }
            if (q > mp) { mp = q; lp = d; }
        }
        lab_i[r2] = li; lab_p[r2] = lp;
    }

    __syncthreads();

    atomicAdd(&hin[lab_i[0]], 1);   atomicAdd(&hin[lab_i[1]], 1);
    atomicAdd(&hpred[lab_p[0]], 1); atomicAdd(&hpred[lab_p[1]], 1);

    // ---- NN scan: input-half threads scan sB, pred-half scan sA ----
    const bool isInput = (t < HALF);
    const float* sarr  = isInput ? sB : sA;
    const float* qbase = isInput ? kine_input : kine_pred;
    const int th = isInput ? t : (t - HALF);

    u64 qx[QPT], qy[QPT], qz[QPT], qw[QPT], qc[QPT];
    #pragma unroll
    for (int qi = 0; qi < QPT; qi++) {
        float4 q = reinterpret_cast<const float4*>(qbase)[b * NPTS + th + HALF * qi];
        float n = q.x * q.x + q.y * q.y + q.z * q.z + q.w * q.w;
        qx[qi] = pack2(q.x, q.x); qy[qi] = pack2(q.y, q.y);
        qz[qi] = pack2(q.z, q.z); qw[qi] = pack2(q.w, q.w);
        qc[qi] = pack2(n, n);
    }
    const u64 M2 = pack2(-2.0f, -2.0f);

    float gmin[QPT]; int gch[QPT];
    #pragma unroll
    for (int qi = 0; qi < QPT; qi++) { gmin[qi] = 3.402823466e38f; gch[qi] = 0; }

    #pragma unroll 1
    for (int c = 0; c < NCHUNK; c++) {
        float cm[QPT];
        #pragma unroll
        for (int qi = 0; qi < QPT; qi++) cm[qi] = 3.402823466e38f;
        const ulonglong2* cp = reinterpret_cast<const ulonglong2*>(sarr + c * (CE * EF));
        #pragma unroll
        for (int e = 0; e < CE; e++) {
            ulonglong2 vx = cp[e * 5 + 0], vy = cp[e * 5 + 1], vz = cp[e * 5 + 2],
                       vw = cp[e * 5 + 3], vn = cp[e * 5 + 4];
            #pragma unroll
            for (int qi = 0; qi < QPT; qi++) {
                u64 d0 = ffma2(qw[qi], vw.x, ffma2(qz[qi], vz.x, ffma2(qy[qi], vy.x, fmul2(qx[qi], vx.x))));
                u64 v0 = ffma2(M2, d0, fadd2(qc[qi], vn.x));
                u64 d1 = ffma2(qw[qi], vw.y, ffma2(qz[qi], vz.y, ffma2(qy[qi], vy.y, fmul2(qx[qi], vx.y))));
                u64 v1 = ffma2(M2, d1, fadd2(qc[qi], vn.y));
                float2 a = unpack2(v0);
                float2 d = unpack2(v1);
                cm[qi] = fminf(cm[qi], fminf(fminf(a.x, a.y), fminf(d.x, d.y)));
            }
        }
        #pragma unroll
        for (int qi = 0; qi < QPT; qi++)
            if (cm[qi] < gmin[qi]) { gmin[qi] = cm[qi]; gch[qi] = c; }
    }

    // ---- rescan winning chunk per query (identical arithmetic) for first index ----
    float dist[QPT]; int bidx[QPT];
    #pragma unroll
    for (int qi = 0; qi < QPT; qi++) {
        int id = -1;
        const ulonglong2* cp = reinterpret_cast<const ulonglong2*>(sarr + gch[qi] * (CE * EF));
        #pragma unroll
        for (int e = 0; e < CE; e++) {
            ulonglong2 vx = cp[e * 5 + 0], vy = cp[e * 5 + 1], vz = cp[e * 5 + 2],
                       vw = cp[e * 5 + 3], vn = cp[e * 5 + 4];
            u64 d0 = ffma2(qw[qi], vw.x, ffma2(qz[qi], vz.x, ffma2(qy[qi], vy.x, fmul2(qx[qi], vx.x))));
            u64 v0 = ffma2(M2, d0, fadd2(qc[qi], vn.x));
            u64 d1 = ffma2(qw[qi], vw.y, ffma2(qz[qi], vz.y, ffma2(qy[qi], vy.y, fmul2(qx[qi], vx.y))));
            u64 v1 = ffma2(M2, d1, fadd2(qc[qi], vn.y));
            float2 a = unpack2(v0);
            float2 d = unpack2(v1);
            int base = gch[qi] * (CE * 4) + e * 4;
            if (id < 0 && a.x == gmin[qi]) id = base + 0;
            if (id < 0 && a.y == gmin[qi]) id = base + 1;
            if (id < 0 && d.x == gmin[qi]) id = base + 2;
            if (id < 0 && d.y == gmin[qi]) id = base + 3;
        }
        bidx[qi] = (id < 0) ? 0 : id;
        dist[qi] = fmaxf(gmin[qi], 0.0f);
    }

    // ---- classification gathers + per-thread partial ----
    const float* gatherArr = isInput ? class_pred : class_input;
    const float* ownArr    = isInput ? class_input : class_pred;
    float r = 0.0f;
    #pragma unroll
    for (int qi = 0; qi < QPT; qi++) {
        const float* g = gatherArr + ((size_t)b * NPTS + bidx[qi]) * DCLS;
        const float* o = ownArr    + ((size_t)b * NPTS + th + HALF * qi) * DCLS;
        float s = 0.0f;
        #pragma unroll
        for (int d = 0; d < DCLS; d++) s = fmaf(g[d], o[d], s);
        r += dist[qi] - s;
    }

    // ---- block reduction (8 warps) ----
    const int lane = t & 31;
    const int wid  = t >> 5;
    float v = warpReduceSum(r);
    if (lane == 0) red[wid] = v;
    __syncthreads();
    if (wid == 0) {
        v = (lane < 8) ? red[lane] : 0.0f;
        v = warpReduceSum(v);
        if (lane == 0) red[0] = v;
    }
    __syncthreads();

    if (t == 0) {
        float S = red[0];   // chamfer_loss + class_loss

        float cn;
        {
            float d0 = fabsf((float)(hpred[0] - hin[0]));
            float d8 = fabsf((float)(hpred[DCLS - 1] - hin[DCLS - 1]));
            cn = d0 * 2.0f + d8 * 100.0f;
            #pragma unroll
            for (int c = 1; c < DCLS - 1; c++)
                cn += fabsf((float)(hpred[c] - hin[c]));
        }

        float kl = 0.0f;
        const float* mub = mu      + (size_t)b * LLAT;
        const float* lvb = log_var + (size_t)b * LLAT;
        #pragma unroll
        for (int l = 0; l < LLAT; l++) {
            float m  = mub[l];
            float lv = lvb[l];
            kl += 1.0f + lv - m * m - expf(lv);
        }
        kl = -0.5f * kl;

        out[b] = 0.99f * (S + 0.001f * cn) + 0.01f * kl;
    }
}

extern "C" void kernel_launch(void* const* d_in, const int* in_sizes, int n_in,
                              void* d_out, int out_size)
{
    const float* kine_input  = (const float*)d_in[0];
    const float* class_input = (const float*)d_in[1];
    const float* kine_pred   = (const float*)d_in[2];
    const float* class_pred  = (const float*)d_in[3];
    const float* mu          = (const float*)d_in[4];
    const float* log_var     = (const float*)d_in[5];

    const int B = in_sizes[4] / LLAT;   // mu is [B, 32]

    loss_kernel<<<B, THREADS>>>(kine_input, class_input, kine_pred, class_pred,
                                mu, log_var, (float*)d_out);
}